// round 14
// baseline (speedup 1.0000x reference)
#include <cuda_runtime.h>
#include <cuda_bf16.h>
#include <cstdint>
#include <cstddef>

// CriticRNN: T=128, NE=64, NA=8, OBS=64, D=128, CH=128, VH=256, ITERS=2, B=512
// Round 14: tensor-core GRU (bf16-split 3-mma, Wh resident as packed B-frags)
// + R9-config GEMM kernels (256 thr, MT=4, ping-pong).

#define TBROWS 65536
typedef unsigned long long ull;

__device__ float g_gi[(size_t)TBROWS * 384];
__device__ float g_e [(size_t)TBROWS * 128];

__device__ __forceinline__ uint32_t f2tf32(float x) {
    uint32_t u; asm("cvt.rna.tf32.f32 %0, %1;" : "=r"(u) : "f"(x)); return u;
}
__device__ __forceinline__ void mma8(float c[4],
    uint32_t a0, uint32_t a1, uint32_t a2, uint32_t a3, uint32_t b0, uint32_t b1)
{
    asm volatile(
        "mma.sync.aligned.m16n8k8.row.col.f32.tf32.tf32.f32 "
        "{%0,%1,%2,%3},{%4,%5,%6,%7},{%8,%9},{%0,%1,%2,%3};"
        : "+f"(c[0]), "+f"(c[1]), "+f"(c[2]), "+f"(c[3])
        : "r"(a0), "r"(a1), "r"(a2), "r"(a3), "r"(b0), "r"(b1));
}
__device__ __forceinline__ void mmabf(float c[4],
    uint32_t a0, uint32_t a1, uint32_t a2, uint32_t a3, uint32_t b0, uint32_t b1)
{
    asm volatile(
        "mma.sync.aligned.m16n8k16.row.col.f32.bf16.bf16.f32 "
        "{%0,%1,%2,%3},{%4,%5,%6,%7},{%8,%9},{%0,%1,%2,%3};"
        : "+f"(c[0]), "+f"(c[1]), "+f"(c[2]), "+f"(c[3])
        : "r"(a0), "r"(a1), "r"(a2), "r"(a3), "r"(b0), "r"(b1));
}
__device__ __forceinline__ float fsig(float x) {
    return __fdividef(1.f, 1.f + __expf(-x));
}
__device__ __forceinline__ float ftanh(float x) {
    const float e = __expf(-2.f * x);
    return __fdividef(1.f - e, 1.f + e);
}
__device__ __forceinline__ float bf_lo(uint32_t u) {
    return __bfloat162float(__ushort_as_bfloat16((unsigned short)(u & 0xffffu)));
}
__device__ __forceinline__ float bf_hi(uint32_t u) {
    return __bfloat162float(__ushort_as_bfloat16((unsigned short)(u >> 16)));
}
// pack (a,b) to bf16x2 hi word; residuals out
__device__ __forceinline__ uint32_t pk_hi(float a, float b, float& ra, float& rb) {
    const __nv_bfloat16 ha = __float2bfloat16(a), hb = __float2bfloat16(b);
    ra = a - __bfloat162float(ha);
    rb = b - __bfloat162float(hb);
    return ((uint32_t)__bfloat16_as_ushort(hb) << 16) | __bfloat16_as_ushort(ha);
}
__device__ __forceinline__ uint32_t pk_bf2(float a, float b) {
    const __nv_bfloat16 ha = __float2bfloat16(a), hb = __float2bfloat16(b);
    return ((uint32_t)__bfloat16_as_ushort(hb) << 16) | __bfloat16_as_ushort(ha);
}

// packed A-frag word index for (row 0..15, k-pair k2 0..63)
__device__ __forceinline__ int widxA(int row, int k2) {
    const int kstep = k2 >> 3, k2l = k2 & 7;
    const int tt = k2l & 3, sel = k2l >> 2;
    const int reg = (row >> 3) + 2 * sel;
    const int ln = (row & 7) * 4 + tt;
    return (kstep * 32 + ln) * 4 + reg;
}
// packed B-frag word index for (n 0..383, k2 0..63)
__device__ __forceinline__ int widxB(int n, int k2) {
    const int kstep = k2 >> 3, k2l = k2 & 7;
    const int tt = k2l & 3, sel = k2l >> 2;
    const int ln = (n & 7) * 4 + tt;
    return (((n >> 3) * 4 + (kstep >> 1)) * 32 + ln) * 4 + (kstep & 1) * 2 + sel;
}

// ===== tf32 GEMM blocks (R9 config): tile 128x128, 8 warps (2m x 4n) =====

__device__ __forceinline__ void acc_zero(float (&acc)[4][4][4]) {
#pragma unroll
    for (int mt = 0; mt < 4; mt++)
#pragma unroll
        for (int nt = 0; nt < 4; nt++)
#pragma unroll
            for (int q = 0; q < 4; q++) acc[mt][nt][q] = 0.f;
}

__device__ __forceinline__ void compute_chunk(
    const uint32_t* __restrict__ asrc, int astr, const uint32_t* __restrict__ Bs,
    float (&acc)[4][4][4], int wm0, int wn0, int g, int t4)
{
#pragma unroll
    for (int ks = 0; ks < 4; ks++) {
        const int kc = ks * 8 + t4;
        uint32_t af[4][4], bf[4][2];
#pragma unroll
        for (int mt = 0; mt < 4; mt++) {
            const int r = wm0 + mt * 16 + g;
            af[mt][0] = asrc[r * astr + kc];
            af[mt][1] = asrc[(r + 8) * astr + kc];
            af[mt][2] = asrc[r * astr + kc + 4];
            af[mt][3] = asrc[(r + 8) * astr + kc + 4];
        }
#pragma unroll
        for (int nt = 0; nt < 4; nt++) {
            const int c = wn0 + nt * 8 + g;
            bf[nt][0] = Bs[kc * 136 + c];
            bf[nt][1] = Bs[(kc + 4) * 136 + c];
        }
#pragma unroll
        for (int mt = 0; mt < 4; mt++)
#pragma unroll
            for (int nt = 0; nt < 4; nt++)
                mma8(acc[mt][nt], af[mt][0], af[mt][1], af[mt][2], af[mt][3],
                     bf[nt][0], bf[nt][1]);
    }
}

#define LDGA(k0)                                                               \
    _Pragma("unroll")                                                          \
    for (int i = 0; i < 4; i++) {                                              \
        const int f = i * 256 + tid; const int r = f >> 3, c = (f & 7) << 2;   \
        pa[i] = *(const float4*)(A + (size_t)r * lda + (k0) + c);              \
    }
#define LDGB(k0)                                                               \
    _Pragma("unroll")                                                          \
    for (int i = 0; i < 4; i++) {                                              \
        const int f = i * 256 + tid; const int r = f >> 5, c = (f & 31) << 2;  \
        pb[i] = *(const float4*)(B + (size_t)((k0) + r) * ldb + c);            \
    }
#define STSA(dst)                                                              \
    _Pragma("unroll")                                                          \
    for (int i = 0; i < 4; i++) {                                              \
        const int f = i * 256 + tid; const int r = f >> 3, c = (f & 7) << 2;   \
        uint4 v; v.x = f2tf32(pa[i].x); v.y = f2tf32(pa[i].y);                 \
        v.z = f2tf32(pa[i].z); v.w = f2tf32(pa[i].w);                          \
        *(uint4*)&(dst)[r * 36 + c] = v;                                       \
    }
#define STSB(dst)                                                              \
    _Pragma("unroll")                                                          \
    for (int i = 0; i < 4; i++) {                                              \
        const int f = i * 256 + tid; const int r = f >> 5, c = (f & 31) << 2;  \
        uint4 v; v.x = f2tf32(pb[i].x); v.y = f2tf32(pb[i].y);                 \
        v.z = f2tf32(pb[i].z); v.w = f2tf32(pb[i].w);                          \
        *(uint4*)&(dst)[r * 136 + c] = v;                                      \
    }

__device__ __forceinline__ void gemm_gmemA(
    const float* __restrict__ A, int lda, int K,
    const float* __restrict__ B, int ldb,
    uint32_t* As0, uint32_t* As1, uint32_t* Bs0, uint32_t* Bs1,
    float (&acc)[4][4][4], int tid, int wm0, int wn0, int g, int t4)
{
    acc_zero(acc);
    float4 pa[4], pb[4];
    const int nch = K >> 5;
    uint32_t *Ac = As0, *An = As1, *Bc = Bs0, *Bn = Bs1;
    __syncthreads();
    LDGA(0) LDGB(0)
    STSA(Ac) STSB(Bc)
    __syncthreads();
    for (int ch = 1; ch < nch; ch++) {
        LDGA(ch * 32) LDGB(ch * 32)
        compute_chunk(Ac, 36, Bc, acc, wm0, wn0, g, t4);
        STSA(An) STSB(Bn)
        __syncthreads();
        uint32_t* t;
        t = Ac; Ac = An; An = t;
        t = Bc; Bc = Bn; Bn = t;
    }
    compute_chunk(Ac, 36, Bc, acc, wm0, wn0, g, t4);
}

__device__ __forceinline__ void gemm_smemA(
    const uint32_t* __restrict__ Asrc, int astr, int K,
    const float* __restrict__ B, int ldb,
    uint32_t* Bs0, uint32_t* Bs1,
    float (&acc)[4][4][4], int tid, int wm0, int wn0, int g, int t4)
{
    acc_zero(acc);
    float4 pb[4];
    const int nch = K >> 5;
    uint32_t *Bc = Bs0, *Bn = Bs1;
    __syncthreads();
    LDGB(0)
    STSB(Bc)
    __syncthreads();
    for (int ch = 1; ch < nch; ch++) {
        LDGB(ch * 32)
        compute_chunk(Asrc + (ch - 1) * 32, astr, Bc, acc, wm0, wn0, g, t4);
        STSB(Bn)
        __syncthreads();
        uint32_t* t = Bc; Bc = Bn; Bn = t;
    }
    compute_chunk(Asrc + (nch - 1) * 32, astr, Bc, acc, wm0, wn0, g, t4);
}

// ================= embed_gi (R9 config) =================
__global__ __launch_bounds__(256) void embed_gi_fused(
    const float* __restrict__ obs,
    const float* __restrict__ e1w, const float* __restrict__ e1b,
    const float* __restrict__ e2w, const float* __restrict__ e2b,
    const float* __restrict__ Wi,  const float* __restrict__ bi,
    float* __restrict__ gi)
{
    extern __shared__ unsigned char smraw[];
    uint32_t* As0 = (uint32_t*)smraw;
    uint32_t* As1 = As0 + 128 * 36;
    uint32_t* Bs0 = As1 + 128 * 36;
    uint32_t* Bs1 = Bs0 + 32 * 136;
    uint32_t* s1  = Bs1 + 32 * 136;

    const int tid = threadIdx.x;
    const int warp = tid >> 5, lane = tid & 31;
    const int g = lane >> 2, t4 = lane & 3;
    const int wm0 = (warp >> 2) * 64, wn0 = (warp & 3) * 32;
    const int br0 = blockIdx.x * 128;
    float acc[4][4][4];

    gemm_gmemA(obs + (size_t)br0 * 64, 64, 64, e1w, 128,
               As0, As1, Bs0, Bs1, acc, tid, wm0, wn0, g, t4);
    __syncthreads();
#pragma unroll
    for (int mt = 0; mt < 4; mt++)
#pragma unroll
        for (int nt = 0; nt < 4; nt++) {
            const int r0 = wm0 + mt * 16 + g, c0 = wn0 + nt * 8 + 2 * t4;
            const float b0 = e1b[c0], b1 = e1b[c0 + 1];
            s1[r0 * 132 + c0]           = f2tf32(fmaxf(acc[mt][nt][0] + b0, 0.f));
            s1[r0 * 132 + c0 + 1]       = f2tf32(fmaxf(acc[mt][nt][1] + b1, 0.f));
            s1[(r0 + 8) * 132 + c0]     = f2tf32(fmaxf(acc[mt][nt][2] + b0, 0.f));
            s1[(r0 + 8) * 132 + c0 + 1] = f2tf32(fmaxf(acc[mt][nt][3] + b1, 0.f));
        }

    gemm_smemA(s1, 132, 128, e2w, 128, Bs0, Bs1, acc, tid, wm0, wn0, g, t4);
    __syncthreads();
#pragma unroll
    for (int mt = 0; mt < 4; mt++)
#pragma unroll
        for (int nt = 0; nt < 4; nt++) {
            const int r0 = wm0 + mt * 16 + g, c0 = wn0 + nt * 8 + 2 * t4;
            const float b0 = e2b[c0], b1 = e2b[c0 + 1];
            s1[r0 * 132 + c0]           = f2tf32(fmaxf(acc[mt][nt][0] + b0, 0.f));
            s1[r0 * 132 + c0 + 1]       = f2tf32(fmaxf(acc[mt][nt][1] + b1, 0.f));
            s1[(r0 + 8) * 132 + c0]     = f2tf32(fmaxf(acc[mt][nt][2] + b0, 0.f));
            s1[(r0 + 8) * 132 + c0 + 1] = f2tf32(fmaxf(acc[mt][nt][3] + b1, 0.f));
        }

    for (int p = 0; p < 3; p++) {
        gemm_smemA(s1, 132, 128, Wi + p * 128, 384, Bs0, Bs1, acc, tid, wm0, wn0, g, t4);
#pragma unroll
        for (int mt = 0; mt < 4; mt++)
#pragma unroll
            for (int nt = 0; nt < 4; nt++) {
                const int r0 = wm0 + mt * 16 + g, c0 = wn0 + nt * 8 + 2 * t4;
                const int cg = p * 128 + c0;
                const float b0 = bi[cg], b1 = bi[cg + 1];
                float2 o0 = {acc[mt][nt][0] + b0, acc[mt][nt][1] + b1};
                float2 o1 = {acc[mt][nt][2] + b0, acc[mt][nt][3] + b1};
                *(float2*)(gi + (size_t)(br0 + r0) * 384 + cg) = o0;
                *(float2*)(gi + (size_t)(br0 + r0 + 8) * 384 + cg) = o1;
            }
    }
}

// ================= tensor-core GRU =================
// 32 CTAs x 16 rows, 256 threads (8 warps x 16x48 gh tile).
// gh = h @ Wh via bf16-split 3-mma; Wh resident in smem as packed B-frags.
__global__ __launch_bounds__(256) void gru_tc(
    const float* __restrict__ gi, const int* __restrict__ dones,
    const float* __restrict__ Wh, const float* __restrict__ bhn,
    const float* __restrict__ h0, float* __restrict__ e_out, float* __restrict__ h_out)
{
    extern __shared__ uint32_t sg[];
    uint32_t* Whi = sg;                 // 48*4*32*4 = 24576 words
    uint32_t* Wlo = Whi + 24576;        // 24576
    uint32_t* Ahi = Wlo + 24576;        // 8*32*4 = 1024
    uint32_t* Alo = Ahi + 1024;         // 1024
    float* ghx = (float*)(Alo + 1024);  // 16*392 = 6272 floats

    const int tid = threadIdx.x;
    const int warp = tid >> 5, lane = tid & 31;
    const int rb = blockIdx.x * 16;

    // ---- one-time: pack Wh into bf16 hi/lo B-fragment layout ----
    for (int idx = tid; idx < 64 * 384; idx += 256) {
        const int k2 = idx / 384, n = idx - k2 * 384;
        const float wa = Wh[(size_t)(2 * k2) * 384 + n];
        const float wb = Wh[(size_t)(2 * k2 + 1) * 384 + n];
        float ra, rbv;
        const int w = widxB(n, k2);
        Whi[w] = pk_hi(wa, wb, ra, rbv);
        Wlo[w] = pk_bf2(ra, rbv);
    }

    // gate-phase thread mapping (also used for h0 init)
    const int row = tid >> 4;                  // 0..15
    const int cseg = (tid & 15) * 8;           // 0..120
    const int grow = rb + row;
    int wa4[4];
#pragma unroll
    for (int p = 0; p < 4; p++) wa4[p] = widxA(row, (cseg >> 1) + p);

    // bhn for my cols (constant)
    float bhv[8];
    {
        const float4 b0 = *(const float4*)(bhn + cseg);
        const float4 b1 = *(const float4*)(bhn + cseg + 4);
        bhv[0]=b0.x; bhv[1]=b0.y; bhv[2]=b0.z; bhv[3]=b0.w;
        bhv[4]=b1.x; bhv[5]=b1.y; bhv[6]=b1.z; bhv[7]=b1.w;
    }

    // h0 init (masked by dones[0]) into packed A
    {
        const int d0 = dones[grow];
        const float4 h0a = *(const float4*)(h0 + (size_t)grow * 128 + cseg);
        const float4 h0b = *(const float4*)(h0 + (size_t)grow * 128 + cseg + 4);
        float hv[8] = {h0a.x, h0a.y, h0a.z, h0a.w, h0b.x, h0b.y, h0b.z, h0b.w};
#pragma unroll
        for (int i = 0; i < 8; i++) if (d0) hv[i] = 0.f;
#pragma unroll
        for (int p = 0; p < 4; p++) {
            float ra, rbv;
            Ahi[wa4[p]] = pk_hi(hv[2 * p], hv[2 * p + 1], ra, rbv);
            Alo[wa4[p]] = pk_bf2(ra, rbv);
        }
    }
    __syncthreads();

    for (int t = 0; t < 128; t++) {
        // gi prefetch (registers; consumed after mma)
        const float* gp = gi + ((size_t)(t * 512 + grow)) * 384 + cseg;
        const float4 Gr0 = *(const float4*)gp;
        const float4 Gr1 = *(const float4*)(gp + 4);
        const float4 Gz0 = *(const float4*)(gp + 128);
        const float4 Gz1 = *(const float4*)(gp + 132);
        const float4 Gn0 = *(const float4*)(gp + 256);
        const float4 Gn1 = *(const float4*)(gp + 260);
        const int dc = dones[t * 512 + grow];
        const int dn = (t < 127) ? dones[(t + 1) * 512 + grow] : 0;

        // A-frag preload (hi, lo)
        uint4 ah[8], al[8];
#pragma unroll
        for (int ks = 0; ks < 8; ks++) {
            ah[ks] = *(const uint4*)&Ahi[(ks * 32 + lane) * 4];
            al[ks] = *(const uint4*)&Alo[(ks * 32 + lane) * 4];
        }

        float acc[6][4];
#pragma unroll
        for (int nt = 0; nt < 6; nt++)
#pragma unroll
            for (int q = 0; q < 4; q++) acc[nt][q] = 0.f;

#pragma unroll
        for (int nt = 0; nt < 6; nt++) {
#pragma unroll
            for (int k32 = 0; k32 < 4; k32++) {
                const int wb = (((warp * 6 + nt) * 4 + k32) * 32 + lane) * 4;
                const uint4 bh = *(const uint4*)&Whi[wb];
                const uint4 bl = *(const uint4*)&Wlo[wb];
                const int ke = 2 * k32, ko = ke + 1;
                mmabf(acc[nt], ah[ke].x, ah[ke].y, ah[ke].z, ah[ke].w, bh.x, bh.y);
                mmabf(acc[nt], al[ke].x, al[ke].y, al[ke].z, al[ke].w, bh.x, bh.y);
                mmabf(acc[nt], ah[ke].x, ah[ke].y, ah[ke].z, ah[ke].w, bl.x, bl.y);
                mmabf(acc[nt], ah[ko].x, ah[ko].y, ah[ko].z, ah[ko].w, bh.z, bh.w);
                mmabf(acc[nt], al[ko].x, al[ko].y, al[ko].z, al[ko].w, bh.z, bh.w);
                mmabf(acc[nt], ah[ko].x, ah[ko].y, ah[ko].z, ah[ko].w, bl.z, bl.w);
            }
        }

        // gh -> smem
        {
            const int g8 = lane >> 2, t4 = lane & 3;
#pragma unroll
            for (int nt = 0; nt < 6; nt++) {
                const int n0 = warp * 48 + nt * 8 + 2 * t4;
                float2 v0 = {acc[nt][0], acc[nt][1]};
                float2 v1 = {acc[nt][2], acc[nt][3]};
                *(float2*)&ghx[g8 * 392 + n0] = v0;
                *(float2*)&ghx[(g8 + 8) * 392 + n0] = v1;
            }
        }
        __syncthreads();

        // gate math
        {
            const float* gx = ghx + row * 392 + cseg;
            const float4 R0 = *(const float4*)gx;
            const float4 R1 = *(const float4*)(gx + 4);
            const float4 Z0 = *(const float4*)(gx + 128);
            const float4 Z1 = *(const float4*)(gx + 132);
            const float4 N0 = *(const float4*)(gx + 256);
            const float4 N1 = *(const float4*)(gx + 260);
            const float ghr[8] = {R0.x,R0.y,R0.z,R0.w,R1.x,R1.y,R1.z,R1.w};
            const float ghz[8] = {Z0.x,Z0.y,Z0.z,Z0.w,Z1.x,Z1.y,Z1.z,Z1.w};
            const float ghn[8] = {N0.x,N0.y,N0.z,N0.w,N1.x,N1.y,N1.z,N1.w};
            const float gir[8] = {Gr0.x,Gr0.y,Gr0.z,Gr0.w,Gr1.x,Gr1.y,Gr1.z,Gr1.w};
            const float giz[8] = {Gz0.x,Gz0.y,Gz0.z,Gz0.w,Gz1.x,Gz1.y,Gz1.z,Gz1.w};
            const float gin[8] = {Gn0.x,Gn0.y,Gn0.z,Gn0.w,Gn1.x,Gn1.y,Gn1.z,Gn1.w};

            float hold[8];
#pragma unroll
            for (int p = 0; p < 4; p++) {
                const uint32_t uh = Ahi[wa4[p]];
                const uint32_t ul = Alo[wa4[p]];
                hold[2 * p]     = bf_lo(uh) + bf_lo(ul);
                hold[2 * p + 1] = bf_hi(uh) + bf_hi(ul);
            }

            float eo[8], hq[8];
#pragma unroll
            for (int i = 0; i < 8; i++) {
                const float r = fsig(gir[i] + ghr[i]);
                const float z = fsig(giz[i] + ghz[i]);
                const float nn = ftanh(gin[i] + r * (ghn[i] + bhv[i]));
                const float h = (1.f - z) * nn + z * hold[i];
                eo[i] = dc ? 0.f : h;
                hq[i] = dn ? 0.f : h;
            }
            float4 E0 = {eo[0], eo[1], eo[2], eo[3]};
            float4 E1 = {eo[4], eo[5], eo[6], eo[7]};
            float* ep = e_out + ((size_t)(t * 512 + grow)) * 128 + cseg;
            *(float4*)ep = E0;
            *(float4*)(ep + 4) = E1;
            if (t == 127) {
                float4 H0v = {hq[0], hq[1], hq[2], hq[3]};
                float4 H1v = {hq[4], hq[5], hq[6], hq[7]};
                float* hp = h_out + (size_t)grow * 128 + cseg;
                *(float4*)hp = H0v;
                *(float4*)(hp + 4) = H1v;
            }
#pragma unroll
            for (int p = 0; p < 4; p++) {
                float ra, rbv;
                Ahi[wa4[p]] = pk_hi(hq[2 * p], hq[2 * p + 1], ra, rbv);
                Alo[wa4[p]] = pk_bf2(ra, rbv);
            }
        }
        __syncthreads();
    }
}

// ============ mega (R9 config): 2x(couple+delta) + value head ============
__global__ __launch_bounds__(256) void post_gru_mega(
    float* __restrict__ e, const int* __restrict__ dones,
    const float* __restrict__ chw, const float* __restrict__ chb,
    const float* __restrict__ cow, const float* __restrict__ cob,
    const float* __restrict__ uhw, const float* __restrict__ uhb,
    const float* __restrict__ uow, const float* __restrict__ uob,
    const float* __restrict__ v1w, const float* __restrict__ v1b,
    const float* __restrict__ v2w, const float* __restrict__ v2b,
    const float* __restrict__ vow, const float* __restrict__ vob,
    float* __restrict__ values)
{
    extern __shared__ unsigned char smraw[];
    uint32_t* As0 = (uint32_t*)smraw;
    uint32_t* As1 = As0 + 128 * 36;
    uint32_t* Bs0 = As1 + 128 * 36;
    uint32_t* Bs1 = Bs0 + 32 * 136;
    uint32_t* U   = Bs1 + 32 * 136;              // 128*264 union
    float* sC     = (float*)(U + 128 * 264);
    float* salive = sC + 1024;
    float* scb    = salive + 128;
    float* sw     = scb + 128;
    float* sred   = sw + 128;
    float* sai    = (float*)U;
    float* saj    = sai + 128 * 132;

    const int tid = threadIdx.x;
    const int warp = tid >> 5, lane = tid & 31;
    const int g = lane >> 2, t4 = lane & 3;
    const int wm0 = (warp >> 2) * 64, wn0 = (warp & 3) * 32;
    const int br0 = blockIdx.x * 128;
    float acc[4][4][4];

    if (tid < 128) {
        scb[tid] = chb[tid];
        sw[tid]  = cow[tid];
        salive[tid] = (dones[br0 + tid] == 0) ? 1.f : 0.f;
    }
    const float cob0 = __ldg(cob);

    for (int it = 0; it < 2; it++) {
        for (int p = 0; p < 2; p++) {
            gemm_gmemA(e + (size_t)br0 * 128, 128, 128, chw + p * 128 * 128, 128,
                       As0, As1, Bs0, Bs1, acc, tid, wm0, wn0, g, t4);
            float* dst = p ? saj : sai;
#pragma unroll
            for (int mt = 0; mt < 4; mt++)
#pragma unroll
                for (int nt = 0; nt < 4; nt++) {
                    const int r0 = wm0 + mt * 16 + g, c0 = wn0 + nt * 8 + 2 * t4;
                    dst[r0 * 132 + c0]           = acc[mt][nt][0];
                    dst[r0 * 132 + c0 + 1]       = acc[mt][nt][1];
                    dst[(r0 + 8) * 132 + c0]     = acc[mt][nt][2];
                    dst[(r0 + 8) * 132 + c0 + 1] = acc[mt][nt][3];
                }
        }
        __syncthreads();

        // pairwise: 16 groups x 64 pairs
        {
            const int grp = tid >> 4, s = tid & 15;
            const int i = s >> 1, jh = s & 1;
            float a4[4] = {0.f, 0.f, 0.f, 0.f};
#pragma unroll 8
            for (int h = 0; h < 128; h += 4) {
                const float4 av = *(const float4*)&sai[(grp * 8 + i) * 132 + h];
                const float4 cb = *(const float4*)&scb[h];
                const float4 wv = *(const float4*)&sw[h];
#pragma unroll
                for (int jj = 0; jj < 4; jj++) {
                    const int j = jh * 4 + jj;
                    const float4 bv = *(const float4*)&saj[(grp * 8 + j) * 132 + h];
                    a4[jj] = fmaf(fmaxf(av.x + bv.x + cb.x, 0.f), wv.x, a4[jj]);
                    a4[jj] = fmaf(fmaxf(av.y + bv.y + cb.y, 0.f), wv.y, a4[jj]);
                    a4[jj] = fmaf(fmaxf(av.z + bv.z + cb.z, 0.f), wv.z, a4[jj]);
                    a4[jj] = fmaf(fmaxf(av.w + bv.w + cb.w, 0.f), wv.w, a4[jj]);
                }
            }
#pragma unroll
            for (int jj = 0; jj < 4; jj++) {
                const int j = jh * 4 + jj;
                float c = fsig(a4[jj] + cob0);
                c *= salive[grp * 8 + j];
                if (i == j) c = 0.f;
                sC[grp * 64 + i * 8 + j] = c;
            }
        }
        __syncthreads();

        // context -> cat (tf32, stride 264) over U
        {
            const int colt = tid & 127, gh = tid >> 7;
#pragma unroll
            for (int gg = 0; gg < 8; gg++) {
                const int grp = gh * 8 + gg;
                const int rbase = br0 + grp * 8;
                float ev[8];
#pragma unroll
                for (int j = 0; j < 8; j++) ev[j] = e[(size_t)(rbase + j) * 128 + colt];
#pragma unroll
                for (int i = 0; i < 8; i++) {
                    float ctx = 0.f;
#pragma unroll
                    for (int j = 0; j < 8; j++)
                        ctx = fmaf(sC[grp * 64 + i * 8 + j], ev[j], ctx);
                    U[(grp * 8 + i) * 264 + colt]       = f2tf32(ev[i]);
                    U[(grp * 8 + i) * 264 + 128 + colt] = f2tf32(ctx);
                }
            }
        }

        gemm_smemA(U, 264, 256, uhw, 128, Bs0, Bs1, acc, tid, wm0, wn0, g, t4);
        __syncthreads();
#pragma unroll
        for (int mt = 0; mt < 4; mt++)
#pragma unroll
            for (int nt = 0; nt < 4; nt++) {
                const int r0 = wm0 + mt * 16 + g, c0 = wn0 + nt * 8 + 2 * t4;
                const float b0 = uhb[c0], b1 = uhb[c0 + 1];
                U[r0 * 132 + c0]           = f2tf32(fmaxf(acc[mt][nt][0] + b0, 0.f));
                U[r0 * 132 + c0 + 1]       = f2tf32(fmaxf(acc[mt][nt][1] + b1, 0.f));
                U[(r0 + 8) * 132 + c0]     = f2tf32(fmaxf(acc[mt][nt][2] + b0, 0.f));
                U[(r0 + 8) * 132 + c0 + 1] = f2tf32(fmaxf(acc[mt][nt][3] + b1, 0.f));
            }

        gemm_smemA(U, 132, 128, uow, 128, Bs0, Bs1, acc, tid, wm0, wn0, g, t4);
#pragma unroll
        for (int mt = 0; mt < 4; mt++) {
            const int r0 = wm0 + mt * 16 + g;
            const float al0 = salive[r0];
            const float al1 = salive[r0 + 8];
#pragma unroll
            for (int nt = 0; nt < 4; nt++) {
                const int c0 = wn0 + nt * 8 + 2 * t4;
                const float b0 = uob[c0], b1 = uob[c0 + 1];
                float* p0 = e + (size_t)(br0 + r0) * 128 + c0;
                float* p1 = e + (size_t)(br0 + r0 + 8) * 128 + c0;
                const float2 e0 = *(const float2*)p0;
                const float2 e1 = *(const float2*)p1;
                float2 o0, o1;
                o0.x = (e0.x + fmaxf(acc[mt][nt][0] + b0, 0.f)) * al0;
                o0.y = (e0.y + fmaxf(acc[mt][nt][1] + b1, 0.f)) * al0;
                o1.x = (e1.x + fmaxf(acc[mt][nt][2] + b0, 0.f)) * al1;
                o1.y = (e1.y + fmaxf(acc[mt][nt][3] + b1, 0.f)) * al1;
                *(float2*)p0 = o0;
                *(float2*)p1 = o1;
            }
        }
        __syncthreads();
    }

    for (int p = 0; p < 2; p++) {
        gemm_gmemA(e + (size_t)br0 * 128, 128, 128, v1w + p * 128, 256,
                   As0, As1, Bs0, Bs1, acc, tid, wm0, wn0, g, t4);
#pragma unroll
        for (int mt = 0; mt < 4; mt++)
#pragma unroll
            for (int nt = 0; nt < 4; nt++) {
                const int r0 = wm0 + mt * 16 + g, c0 = wn0 + nt * 8 + 2 * t4;
                const int cg = p * 128 + c0;
                const float b0 = v1b[cg], b1 = v1b[cg + 1];
                U[r0 * 264 + cg]           = f2tf32(fmaxf(acc[mt][nt][0] + b0, 0.f));
                U[r0 * 264 + cg + 1]       = f2tf32(fmaxf(acc[mt][nt][1] + b1, 0.f));
                U[(r0 + 8) * 264 + cg]     = f2tf32(fmaxf(acc[mt][nt][2] + b0, 0.f));
                U[(r0 + 8) * 264 + cg + 1] = f2tf32(fmaxf(acc[mt][nt][3] + b1, 0.f));
            }
    }

    float part[4][2];
#pragma unroll
    for (int mt = 0; mt < 4; mt++) { part[mt][0] = 0.f; part[mt][1] = 0.f; }
    for (int p = 0; p < 2; p++) {
        gemm_smemA(U, 264, 256, v2w + p * 128, 256, Bs0, Bs1, acc, tid, wm0, wn0, g, t4);
#pragma unroll
        for (int mt = 0; mt < 4; mt++)
#pragma unroll
            for (int nt = 0; nt < 4; nt++) {
                const int c0 = wn0 + nt * 8 + 2 * t4;
                const int cg = p * 128 + c0;
                const float b0 = v2b[cg], b1 = v2b[cg + 1];
                const float w0 = vow[cg], w1 = vow[cg + 1];
                part[mt][0] = fmaf(fmaxf(acc[mt][nt][0] + b0, 0.f), w0, part[mt][0]);
                part[mt][0] = fmaf(fmaxf(acc[mt][nt][1] + b1, 0.f), w1, part[mt][0]);
                part[mt][1] = fmaf(fmaxf(acc[mt][nt][2] + b0, 0.f), w0, part[mt][1]);
                part[mt][1] = fmaf(fmaxf(acc[mt][nt][3] + b1, 0.f), w1, part[mt][1]);
            }
    }
#pragma unroll
    for (int mt = 0; mt < 4; mt++)
#pragma unroll
        for (int h = 0; h < 2; h++) {
            part[mt][h] += __shfl_xor_sync(0xffffffffu, part[mt][h], 1);
            part[mt][h] += __shfl_xor_sync(0xffffffffu, part[mt][h], 2);
        }
    __syncthreads();
    if (t4 == 0) {
        const int wn = warp & 3;
#pragma unroll
        for (int mt = 0; mt < 4; mt++)
#pragma unroll
            for (int h = 0; h < 2; h++)
                sred[wn * 128 + wm0 + mt * 16 + g + h * 8] = part[mt][h];
    }
    __syncthreads();
    if (tid < 128) {
        values[br0 + tid] = sred[tid] + sred[128 + tid] + sred[256 + tid]
                          + sred[384 + tid] + __ldg(vob);
    }
}

// ================= launch =================
extern "C" void kernel_launch(void* const* d_in, const int* in_sizes, int n_in,
                              void* d_out, int out_size)
{
    const float* hidden = (const float*)d_in[0];
    const float* obs    = (const float*)d_in[1];
    const int*   dones  = (const int*)d_in[2];
    const float* e1w = (const float*)d_in[3];
    const float* e1b = (const float*)d_in[4];
    const float* e2w = (const float*)d_in[5];
    const float* e2b = (const float*)d_in[6];
    const float* Wi  = (const float*)d_in[7];
    const float* bi  = (const float*)d_in[8];
    const float* Wh  = (const float*)d_in[9];
    const float* bhn = (const float*)d_in[10];
    const float* chw = (const float*)d_in[11];
    const float* chb = (const float*)d_in[12];
    const float* cow = (const float*)d_in[13];
    const float* cob = (const float*)d_in[14];
    const float* uhw = (const float*)d_in[15];
    const float* uhb = (const float*)d_in[16];
    const float* uow = (const float*)d_in[17];
    const float* uob = (const float*)d_in[18];
    const float* v1w = (const float*)d_in[19];
    const float* v1b = (const float*)d_in[20];
    const float* v2w = (const float*)d_in[21];
    const float* v2b = (const float*)d_in[22];
    const float* vow = (const float*)d_in[23];
    const float* vob = (const float*)d_in[24];
    float* out = (float*)d_out;

    float *gi, *e;
    cudaGetSymbolAddress((void**)&gi, g_gi);
    cudaGetSymbolAddress((void**)&e,  g_e);

    const int smE = (2 * 128 * 36 + 2 * 32 * 136 + 128 * 132) * 4;
    const int smM = (2 * 128 * 36 + 2 * 32 * 136 + 128 * 264
                     + 1024 + 128 + 128 + 128 + 512) * 4;
    const int smG = (24576 * 2 + 1024 * 2 + 16 * 392) * 4;   // 229,888 B
    cudaFuncSetAttribute(embed_gi_fused, cudaFuncAttributeMaxDynamicSharedMemorySize, smE);
    cudaFuncSetAttribute(post_gru_mega,  cudaFuncAttributeMaxDynamicSharedMemorySize, smM);
    cudaFuncSetAttribute(gru_tc,         cudaFuncAttributeMaxDynamicSharedMemorySize, smG);

    embed_gi_fused<<<512, 256, smE>>>(obs, e1w, e1b, e2w, e2b, Wi, bi, gi);
    gru_tc<<<32, 256, smG>>>(gi, dones, Wh, bhn, hidden, e, out);
    post_gru_mega<<<512, 256, smM>>>(e, dones, chw, chb, cow, cob,
                                     uhw, uhb, uow, uob,
                                     v1w, v1b, v2w, v2b, vow, vob, out + 65536);
}

// round 15
// speedup vs baseline: 1.0349x; 1.0349x over previous
#include <cuda_runtime.h>
#include <cuda_bf16.h>
#include <cstdint>
#include <cstddef>

// CriticRNN: T=128, NE=64, NA=8, OBS=64, D=128, CH=128, VH=256, ITERS=2, B=512
// Round 15: TC-GRU rebalanced to 768 threads (24 warps, warp tile 16x16,
// A-frags streamed in k-loop) + R9-config embed/mega.

#define TBROWS 65536
typedef unsigned long long ull;

__device__ float g_gi[(size_t)TBROWS * 384];
__device__ float g_e [(size_t)TBROWS * 128];

__device__ __forceinline__ uint32_t f2tf32(float x) {
    uint32_t u; asm("cvt.rna.tf32.f32 %0, %1;" : "=r"(u) : "f"(x)); return u;
}
__device__ __forceinline__ void mma8(float c[4],
    uint32_t a0, uint32_t a1, uint32_t a2, uint32_t a3, uint32_t b0, uint32_t b1)
{
    asm volatile(
        "mma.sync.aligned.m16n8k8.row.col.f32.tf32.tf32.f32 "
        "{%0,%1,%2,%3},{%4,%5,%6,%7},{%8,%9},{%0,%1,%2,%3};"
        : "+f"(c[0]), "+f"(c[1]), "+f"(c[2]), "+f"(c[3])
        : "r"(a0), "r"(a1), "r"(a2), "r"(a3), "r"(b0), "r"(b1));
}
__device__ __forceinline__ void mmabf(float c[4],
    uint32_t a0, uint32_t a1, uint32_t a2, uint32_t a3, uint32_t b0, uint32_t b1)
{
    asm volatile(
        "mma.sync.aligned.m16n8k16.row.col.f32.bf16.bf16.f32 "
        "{%0,%1,%2,%3},{%4,%5,%6,%7},{%8,%9},{%0,%1,%2,%3};"
        : "+f"(c[0]), "+f"(c[1]), "+f"(c[2]), "+f"(c[3])
        : "r"(a0), "r"(a1), "r"(a2), "r"(a3), "r"(b0), "r"(b1));
}
__device__ __forceinline__ float fsig(float x) {
    return __fdividef(1.f, 1.f + __expf(-x));
}
__device__ __forceinline__ float ftanh(float x) {
    const float e = __expf(-2.f * x);
    return __fdividef(1.f - e, 1.f + e);
}
__device__ __forceinline__ float bf_lo(uint32_t u) {
    return __bfloat162float(__ushort_as_bfloat16((unsigned short)(u & 0xffffu)));
}
__device__ __forceinline__ float bf_hi(uint32_t u) {
    return __bfloat162float(__ushort_as_bfloat16((unsigned short)(u >> 16)));
}
__device__ __forceinline__ uint32_t pk_hi(float a, float b, float& ra, float& rb) {
    const __nv_bfloat16 ha = __float2bfloat16(a), hb = __float2bfloat16(b);
    ra = a - __bfloat162float(ha);
    rb = b - __bfloat162float(hb);
    return ((uint32_t)__bfloat16_as_ushort(hb) << 16) | __bfloat16_as_ushort(ha);
}
__device__ __forceinline__ uint32_t pk_bf2(float a, float b) {
    const __nv_bfloat16 ha = __float2bfloat16(a), hb = __float2bfloat16(b);
    return ((uint32_t)__bfloat16_as_ushort(hb) << 16) | __bfloat16_as_ushort(ha);
}

// packed A-frag word index for (row 0..15, k-pair k2 0..63)
__device__ __forceinline__ int widxA(int row, int k2) {
    const int kstep = k2 >> 3, k2l = k2 & 7;
    const int tt = k2l & 3, sel = k2l >> 2;
    const int reg = (row >> 3) + 2 * sel;
    const int ln = (row & 7) * 4 + tt;
    return (kstep * 32 + ln) * 4 + reg;
}
// packed B-frag word index for (n 0..383, k2 0..63)
__device__ __forceinline__ int widxB(int n, int k2) {
    const int kstep = k2 >> 3, k2l = k2 & 7;
    const int tt = k2l & 3, sel = k2l >> 2;
    const int ln = (n & 7) * 4 + tt;
    return (((n >> 3) * 4 + (kstep >> 1)) * 32 + ln) * 4 + (kstep & 1) * 2 + sel;
}

// ===== tf32 GEMM blocks (R9 config): tile 128x128, 8 warps (2m x 4n) =====

__device__ __forceinline__ void acc_zero(float (&acc)[4][4][4]) {
#pragma unroll
    for (int mt = 0; mt < 4; mt++)
#pragma unroll
        for (int nt = 0; nt < 4; nt++)
#pragma unroll
            for (int q = 0; q < 4; q++) acc[mt][nt][q] = 0.f;
}

__device__ __forceinline__ void compute_chunk(
    const uint32_t* __restrict__ asrc, int astr, const uint32_t* __restrict__ Bs,
    float (&acc)[4][4][4], int wm0, int wn0, int g, int t4)
{
#pragma unroll
    for (int ks = 0; ks < 4; ks++) {
        const int kc = ks * 8 + t4;
        uint32_t af[4][4], bf[4][2];
#pragma unroll
        for (int mt = 0; mt < 4; mt++) {
            const int r = wm0 + mt * 16 + g;
            af[mt][0] = asrc[r * astr + kc];
            af[mt][1] = asrc[(r + 8) * astr + kc];
            af[mt][2] = asrc[r * astr + kc + 4];
            af[mt][3] = asrc[(r + 8) * astr + kc + 4];
        }
#pragma unroll
        for (int nt = 0; nt < 4; nt++) {
            const int c = wn0 + nt * 8 + g;
            bf[nt][0] = Bs[kc * 136 + c];
            bf[nt][1] = Bs[(kc + 4) * 136 + c];
        }
#pragma unroll
        for (int mt = 0; mt < 4; mt++)
#pragma unroll
            for (int nt = 0; nt < 4; nt++)
                mma8(acc[mt][nt], af[mt][0], af[mt][1], af[mt][2], af[mt][3],
                     bf[nt][0], bf[nt][1]);
    }
}

#define LDGA(k0)                                                               \
    _Pragma("unroll")                                                          \
    for (int i = 0; i < 4; i++) {                                              \
        const int f = i * 256 + tid; const int r = f >> 3, c = (f & 7) << 2;   \
        pa[i] = *(const float4*)(A + (size_t)r * lda + (k0) + c);              \
    }
#define LDGB(k0)                                                               \
    _Pragma("unroll")                                                          \
    for (int i = 0; i < 4; i++) {                                              \
        const int f = i * 256 + tid; const int r = f >> 5, c = (f & 31) << 2;  \
        pb[i] = *(const float4*)(B + (size_t)((k0) + r) * ldb + c);            \
    }
#define STSA(dst)                                                              \
    _Pragma("unroll")                                                          \
    for (int i = 0; i < 4; i++) {                                              \
        const int f = i * 256 + tid; const int r = f >> 3, c = (f & 7) << 2;   \
        uint4 v; v.x = f2tf32(pa[i].x); v.y = f2tf32(pa[i].y);                 \
        v.z = f2tf32(pa[i].z); v.w = f2tf32(pa[i].w);                          \
        *(uint4*)&(dst)[r * 36 + c] = v;                                       \
    }
#define STSB(dst)                                                              \
    _Pragma("unroll")                                                          \
    for (int i = 0; i < 4; i++) {                                              \
        const int f = i * 256 + tid; const int r = f >> 5, c = (f & 31) << 2;  \
        uint4 v; v.x = f2tf32(pb[i].x); v.y = f2tf32(pb[i].y);                 \
        v.z = f2tf32(pb[i].z); v.w = f2tf32(pb[i].w);                          \
        *(uint4*)&(dst)[r * 136 + c] = v;                                      \
    }

__device__ __forceinline__ void gemm_gmemA(
    const float* __restrict__ A, int lda, int K,
    const float* __restrict__ B, int ldb,
    uint32_t* As0, uint32_t* As1, uint32_t* Bs0, uint32_t* Bs1,
    float (&acc)[4][4][4], int tid, int wm0, int wn0, int g, int t4)
{
    acc_zero(acc);
    float4 pa[4], pb[4];
    const int nch = K >> 5;
    uint32_t *Ac = As0, *An = As1, *Bc = Bs0, *Bn = Bs1;
    __syncthreads();
    LDGA(0) LDGB(0)
    STSA(Ac) STSB(Bc)
    __syncthreads();
    for (int ch = 1; ch < nch; ch++) {
        LDGA(ch * 32) LDGB(ch * 32)
        compute_chunk(Ac, 36, Bc, acc, wm0, wn0, g, t4);
        STSA(An) STSB(Bn)
        __syncthreads();
        uint32_t* t;
        t = Ac; Ac = An; An = t;
        t = Bc; Bc = Bn; Bn = t;
    }
    compute_chunk(Ac, 36, Bc, acc, wm0, wn0, g, t4);
}

__device__ __forceinline__ void gemm_smemA(
    const uint32_t* __restrict__ Asrc, int astr, int K,
    const float* __restrict__ B, int ldb,
    uint32_t* Bs0, uint32_t* Bs1,
    float (&acc)[4][4][4], int tid, int wm0, int wn0, int g, int t4)
{
    acc_zero(acc);
    float4 pb[4];
    const int nch = K >> 5;
    uint32_t *Bc = Bs0, *Bn = Bs1;
    __syncthreads();
    LDGB(0)
    STSB(Bc)
    __syncthreads();
    for (int ch = 1; ch < nch; ch++) {
        LDGB(ch * 32)
        compute_chunk(Asrc + (ch - 1) * 32, astr, Bc, acc, wm0, wn0, g, t4);
        STSB(Bn)
        __syncthreads();
        uint32_t* t = Bc; Bc = Bn; Bn = t;
    }
    compute_chunk(Asrc + (nch - 1) * 32, astr, Bc, acc, wm0, wn0, g, t4);
}

// ================= embed_gi (R9 config) =================
__global__ __launch_bounds__(256) void embed_gi_fused(
    const float* __restrict__ obs,
    const float* __restrict__ e1w, const float* __restrict__ e1b,
    const float* __restrict__ e2w, const float* __restrict__ e2b,
    const float* __restrict__ Wi,  const float* __restrict__ bi,
    float* __restrict__ gi)
{
    extern __shared__ unsigned char smraw[];
    uint32_t* As0 = (uint32_t*)smraw;
    uint32_t* As1 = As0 + 128 * 36;
    uint32_t* Bs0 = As1 + 128 * 36;
    uint32_t* Bs1 = Bs0 + 32 * 136;
    uint32_t* s1  = Bs1 + 32 * 136;

    const int tid = threadIdx.x;
    const int warp = tid >> 5, lane = tid & 31;
    const int g = lane >> 2, t4 = lane & 3;
    const int wm0 = (warp >> 2) * 64, wn0 = (warp & 3) * 32;
    const int br0 = blockIdx.x * 128;
    float acc[4][4][4];

    gemm_gmemA(obs + (size_t)br0 * 64, 64, 64, e1w, 128,
               As0, As1, Bs0, Bs1, acc, tid, wm0, wn0, g, t4);
    __syncthreads();
#pragma unroll
    for (int mt = 0; mt < 4; mt++)
#pragma unroll
        for (int nt = 0; nt < 4; nt++) {
            const int r0 = wm0 + mt * 16 + g, c0 = wn0 + nt * 8 + 2 * t4;
            const float b0 = e1b[c0], b1 = e1b[c0 + 1];
            s1[r0 * 132 + c0]           = f2tf32(fmaxf(acc[mt][nt][0] + b0, 0.f));
            s1[r0 * 132 + c0 + 1]       = f2tf32(fmaxf(acc[mt][nt][1] + b1, 0.f));
            s1[(r0 + 8) * 132 + c0]     = f2tf32(fmaxf(acc[mt][nt][2] + b0, 0.f));
            s1[(r0 + 8) * 132 + c0 + 1] = f2tf32(fmaxf(acc[mt][nt][3] + b1, 0.f));
        }

    gemm_smemA(s1, 132, 128, e2w, 128, Bs0, Bs1, acc, tid, wm0, wn0, g, t4);
    __syncthreads();
#pragma unroll
    for (int mt = 0; mt < 4; mt++)
#pragma unroll
        for (int nt = 0; nt < 4; nt++) {
            const int r0 = wm0 + mt * 16 + g, c0 = wn0 + nt * 8 + 2 * t4;
            const float b0 = e2b[c0], b1 = e2b[c0 + 1];
            s1[r0 * 132 + c0]           = f2tf32(fmaxf(acc[mt][nt][0] + b0, 0.f));
            s1[r0 * 132 + c0 + 1]       = f2tf32(fmaxf(acc[mt][nt][1] + b1, 0.f));
            s1[(r0 + 8) * 132 + c0]     = f2tf32(fmaxf(acc[mt][nt][2] + b0, 0.f));
            s1[(r0 + 8) * 132 + c0 + 1] = f2tf32(fmaxf(acc[mt][nt][3] + b1, 0.f));
        }

    for (int p = 0; p < 3; p++) {
        gemm_smemA(s1, 132, 128, Wi + p * 128, 384, Bs0, Bs1, acc, tid, wm0, wn0, g, t4);
#pragma unroll
        for (int mt = 0; mt < 4; mt++)
#pragma unroll
            for (int nt = 0; nt < 4; nt++) {
                const int r0 = wm0 + mt * 16 + g, c0 = wn0 + nt * 8 + 2 * t4;
                const int cg = p * 128 + c0;
                const float b0 = bi[cg], b1 = bi[cg + 1];
                float2 o0 = {acc[mt][nt][0] + b0, acc[mt][nt][1] + b1};
                float2 o1 = {acc[mt][nt][2] + b0, acc[mt][nt][3] + b1};
                *(float2*)(gi + (size_t)(br0 + r0) * 384 + cg) = o0;
                *(float2*)(gi + (size_t)(br0 + r0 + 8) * 384 + cg) = o1;
            }
    }
}

// ================= tensor-core GRU v2 =================
// 32 CTAs x 16 rows, 768 threads (24 warps x 16x16 gh tile).
__global__ __launch_bounds__(768) void gru_tc(
    const float* __restrict__ gi, const int* __restrict__ dones,
    const float* __restrict__ Wh, const float* __restrict__ bhn,
    const float* __restrict__ h0, float* __restrict__ e_out, float* __restrict__ h_out)
{
    extern __shared__ uint32_t sg[];
    uint32_t* Whi = sg;                 // 24576 words
    uint32_t* Wlo = Whi + 24576;        // 24576
    uint32_t* Ahi = Wlo + 24576;        // 1024
    uint32_t* Alo = Ahi + 1024;         // 1024
    float* ghx = (float*)(Alo + 1024);  // 16*392

    const int tid = threadIdx.x;
    const int warp = tid >> 5, lane = tid & 31;
    const int rb = blockIdx.x * 16;

    // one-time: pack Wh into bf16 hi/lo B-fragment layout
    for (int idx = tid; idx < 64 * 384; idx += 768) {
        const int k2 = idx / 384, n = idx - k2 * 384;
        const float wa = Wh[(size_t)(2 * k2) * 384 + n];
        const float wb = Wh[(size_t)(2 * k2 + 1) * 384 + n];
        float ra, rbv;
        const int w = widxB(n, k2);
        Whi[w] = pk_hi(wa, wb, ra, rbv);
        Wlo[w] = pk_bf2(ra, rbv);
    }

    // gate-phase mapping: tid<512 -> (row, 4 cols)
    const bool gated = (tid < 512);
    const int row = tid >> 5;                 // 0..15 (valid when gated)
    const int c4 = (tid & 31) * 4;            // 0..124
    const int grow = rb + (gated ? row : 0);
    int wa2[2];
#pragma unroll
    for (int p = 0; p < 2; p++) wa2[p] = widxA(row & 15, (c4 >> 1) + p);

    float bhv[4] = {0.f, 0.f, 0.f, 0.f};
    if (gated) {
        const float4 b0 = *(const float4*)(bhn + c4);
        bhv[0] = b0.x; bhv[1] = b0.y; bhv[2] = b0.z; bhv[3] = b0.w;
    }

    if (gated) {
        const int d0 = dones[grow];
        const float4 hv4 = *(const float4*)(h0 + (size_t)grow * 128 + c4);
        float hv[4] = {hv4.x, hv4.y, hv4.z, hv4.w};
#pragma unroll
        for (int i = 0; i < 4; i++) if (d0) hv[i] = 0.f;
#pragma unroll
        for (int p = 0; p < 2; p++) {
            float ra, rbv;
            Ahi[wa2[p]] = pk_hi(hv[2 * p], hv[2 * p + 1], ra, rbv);
            Alo[wa2[p]] = pk_bf2(ra, rbv);
        }
    }
    __syncthreads();

    for (int t = 0; t < 128; t++) {
        // gi + dones prefetch (tid<512)
        float4 Gr, Gz, Gn;
        int dc = 0, dn = 0;
        if (gated) {
            const float* gp = gi + ((size_t)(t * 512 + grow)) * 384 + c4;
            Gr = *(const float4*)gp;
            Gz = *(const float4*)(gp + 128);
            Gn = *(const float4*)(gp + 256);
            dc = dones[t * 512 + grow];
            dn = (t < 127) ? dones[(t + 1) * 512 + grow] : 0;
        }

        // mma: warp tile 16x16 (nt=2), A-frags streamed per k32
        float acc[2][4];
#pragma unroll
        for (int nt = 0; nt < 2; nt++)
#pragma unroll
            for (int q = 0; q < 4; q++) acc[nt][q] = 0.f;

#pragma unroll
        for (int k32 = 0; k32 < 4; k32++) {
            const int ke = 2 * k32, ko = ke + 1;
            const uint4 ahe = *(const uint4*)&Ahi[(ke * 32 + lane) * 4];
            const uint4 aho = *(const uint4*)&Ahi[(ko * 32 + lane) * 4];
            const uint4 ale = *(const uint4*)&Alo[(ke * 32 + lane) * 4];
            const uint4 alo = *(const uint4*)&Alo[(ko * 32 + lane) * 4];
#pragma unroll
            for (int nt = 0; nt < 2; nt++) {
                const int wb = (((warp * 2 + nt) * 4 + k32) * 32 + lane) * 4;
                const uint4 bh = *(const uint4*)&Whi[wb];
                const uint4 bl = *(const uint4*)&Wlo[wb];
                mmabf(acc[nt], ahe.x, ahe.y, ahe.z, ahe.w, bh.x, bh.y);
                mmabf(acc[nt], ale.x, ale.y, ale.z, ale.w, bh.x, bh.y);
                mmabf(acc[nt], ahe.x, ahe.y, ahe.z, ahe.w, bl.x, bl.y);
                mmabf(acc[nt], aho.x, aho.y, aho.z, aho.w, bh.z, bh.w);
                mmabf(acc[nt], alo.x, alo.y, alo.z, alo.w, bh.z, bh.w);
                mmabf(acc[nt], aho.x, aho.y, aho.z, aho.w, bl.z, bl.w);
            }
        }

        // gh -> smem
        {
            const int g8 = lane >> 2, t4 = lane & 3;
#pragma unroll
            for (int nt = 0; nt < 2; nt++) {
                const int n0 = warp * 16 + nt * 8 + 2 * t4;
                float2 v0 = {acc[nt][0], acc[nt][1]};
                float2 v1 = {acc[nt][2], acc[nt][3]};
                *(float2*)&ghx[g8 * 392 + n0] = v0;
                *(float2*)&ghx[(g8 + 8) * 392 + n0] = v1;
            }
        }
        __syncthreads();

        // gate math (tid<512)
        if (gated) {
            const float* gx = ghx + row * 392 + c4;
            const float4 R = *(const float4*)gx;
            const float4 Z = *(const float4*)(gx + 128);
            const float4 N = *(const float4*)(gx + 256);
            const float ghr[4] = {R.x, R.y, R.z, R.w};
            const float ghz[4] = {Z.x, Z.y, Z.z, Z.w};
            const float ghn[4] = {N.x, N.y, N.z, N.w};
            const float gir[4] = {Gr.x, Gr.y, Gr.z, Gr.w};
            const float giz[4] = {Gz.x, Gz.y, Gz.z, Gz.w};
            const float gin[4] = {Gn.x, Gn.y, Gn.z, Gn.w};

            float hold[4];
#pragma unroll
            for (int p = 0; p < 2; p++) {
                const uint32_t uh = Ahi[wa2[p]];
                const uint32_t ul = Alo[wa2[p]];
                hold[2 * p]     = bf_lo(uh) + bf_lo(ul);
                hold[2 * p + 1] = bf_hi(uh) + bf_hi(ul);
            }

            float eo[4], hq[4];
#pragma unroll
            for (int i = 0; i < 4; i++) {
                const float r = fsig(gir[i] + ghr[i]);
                const float z = fsig(giz[i] + ghz[i]);
                const float nn = ftanh(gin[i] + r * (ghn[i] + bhv[i]));
                const float h = (1.f - z) * nn + z * hold[i];
                eo[i] = dc ? 0.f : h;
                hq[i] = dn ? 0.f : h;
            }
            float4 E = {eo[0], eo[1], eo[2], eo[3]};
            *(float4*)(e_out + ((size_t)(t * 512 + grow)) * 128 + c4) = E;
            if (t == 127) {
                float4 H = {hq[0], hq[1], hq[2], hq[3]};
                *(float4*)(h_out + (size_t)grow * 128 + c4) = H;
            }
#pragma unroll
            for (int p = 0; p < 2; p++) {
                float ra, rbv;
                Ahi[wa2[p]] = pk_hi(hq[2 * p], hq[2 * p + 1], ra, rbv);
                Alo[wa2[p]] = pk_bf2(ra, rbv);
            }
        }
        __syncthreads();
    }
}

// ============ mega (R9 config): 2x(couple+delta) + value head ============
__global__ __launch_bounds__(256) void post_gru_mega(
    float* __restrict__ e, const int* __restrict__ dones,
    const float* __restrict__ chw, const float* __restrict__ chb,
    const float* __restrict__ cow, const float* __restrict__ cob,
    const float* __restrict__ uhw, const float* __restrict__ uhb,
    const float* __restrict__ uow, const float* __restrict__ uob,
    const float* __restrict__ v1w, const float* __restrict__ v1b,
    const float* __restrict__ v2w, const float* __restrict__ v2b,
    const float* __restrict__ vow, const float* __restrict__ vob,
    float* __restrict__ values)
{
    extern __shared__ unsigned char smraw[];
    uint32_t* As0 = (uint32_t*)smraw;
    uint32_t* As1 = As0 + 128 * 36;
    uint32_t* Bs0 = As1 + 128 * 36;
    uint32_t* Bs1 = Bs0 + 32 * 136;
    uint32_t* U   = Bs1 + 32 * 136;
    float* sC     = (float*)(U + 128 * 264);
    float* salive = sC + 1024;
    float* scb    = salive + 128;
    float* sw     = scb + 128;
    float* sred   = sw + 128;
    float* sai    = (float*)U;
    float* saj    = sai + 128 * 132;

    const int tid = threadIdx.x;
    const int warp = tid >> 5, lane = tid & 31;
    const int g = lane >> 2, t4 = lane & 3;
    const int wm0 = (warp >> 2) * 64, wn0 = (warp & 3) * 32;
    const int br0 = blockIdx.x * 128;
    float acc[4][4][4];

    if (tid < 128) {
        scb[tid] = chb[tid];
        sw[tid]  = cow[tid];
        salive[tid] = (dones[br0 + tid] == 0) ? 1.f : 0.f;
    }
    const float cob0 = __ldg(cob);

    for (int it = 0; it < 2; it++) {
        for (int p = 0; p < 2; p++) {
            gemm_gmemA(e + (size_t)br0 * 128, 128, 128, chw + p * 128 * 128, 128,
                       As0, As1, Bs0, Bs1, acc, tid, wm0, wn0, g, t4);
            float* dst = p ? saj : sai;
#pragma unroll
            for (int mt = 0; mt < 4; mt++)
#pragma unroll
                for (int nt = 0; nt < 4; nt++) {
                    const int r0 = wm0 + mt * 16 + g, c0 = wn0 + nt * 8 + 2 * t4;
                    dst[r0 * 132 + c0]           = acc[mt][nt][0];
                    dst[r0 * 132 + c0 + 1]       = acc[mt][nt][1];
                    dst[(r0 + 8) * 132 + c0]     = acc[mt][nt][2];
                    dst[(r0 + 8) * 132 + c0 + 1] = acc[mt][nt][3];
                }
        }
        __syncthreads();

        {
            const int grp = tid >> 4, s = tid & 15;
            const int i = s >> 1, jh = s & 1;
            float a4[4] = {0.f, 0.f, 0.f, 0.f};
#pragma unroll 8
            for (int h = 0; h < 128; h += 4) {
                const float4 av = *(const float4*)&sai[(grp * 8 + i) * 132 + h];
                const float4 cb = *(const float4*)&scb[h];
                const float4 wv = *(const float4*)&sw[h];
#pragma unroll
                for (int jj = 0; jj < 4; jj++) {
                    const int j = jh * 4 + jj;
                    const float4 bv = *(const float4*)&saj[(grp * 8 + j) * 132 + h];
                    a4[jj] = fmaf(fmaxf(av.x + bv.x + cb.x, 0.f), wv.x, a4[jj]);
                    a4[jj] = fmaf(fmaxf(av.y + bv.y + cb.y, 0.f), wv.y, a4[jj]);
                    a4[jj] = fmaf(fmaxf(av.z + bv.z + cb.z, 0.f), wv.z, a4[jj]);
                    a4[jj] = fmaf(fmaxf(av.w + bv.w + cb.w, 0.f), wv.w, a4[jj]);
                }
            }
#pragma unroll
            for (int jj = 0; jj < 4; jj++) {
                const int j = jh * 4 + jj;
                float c = fsig(a4[jj] + cob0);
                c *= salive[grp * 8 + j];
                if (i == j) c = 0.f;
                sC[grp * 64 + i * 8 + j] = c;
            }
        }
        __syncthreads();

        {
            const int colt = tid & 127, gh = tid >> 7;
#pragma unroll
            for (int gg = 0; gg < 8; gg++) {
                const int grp = gh * 8 + gg;
                const int rbase = br0 + grp * 8;
                float ev[8];
#pragma unroll
                for (int j = 0; j < 8; j++) ev[j] = e[(size_t)(rbase + j) * 128 + colt];
#pragma unroll
                for (int i = 0; i < 8; i++) {
                    float ctx = 0.f;
#pragma unroll
                    for (int j = 0; j < 8; j++)
                        ctx = fmaf(sC[grp * 64 + i * 8 + j], ev[j], ctx);
                    U[(grp * 8 + i) * 264 + colt]       = f2tf32(ev[i]);
                    U[(grp * 8 + i) * 264 + 128 + colt] = f2tf32(ctx);
                }
            }
        }

        gemm_smemA(U, 264, 256, uhw, 128, Bs0, Bs1, acc, tid, wm0, wn0, g, t4);
        __syncthreads();
#pragma unroll
        for (int mt = 0; mt < 4; mt++)
#pragma unroll
            for (int nt = 0; nt < 4; nt++) {
                const int r0 = wm0 + mt * 16 + g, c0 = wn0 + nt * 8 + 2 * t4;
                const float b0 = uhb[c0], b1 = uhb[c0 + 1];
                U[r0 * 132 + c0]           = f2tf32(fmaxf(acc[mt][nt][0] + b0, 0.f));
                U[r0 * 132 + c0 + 1]       = f2tf32(fmaxf(acc[mt][nt][1] + b1, 0.f));
                U[(r0 + 8) * 132 + c0]     = f2tf32(fmaxf(acc[mt][nt][2] + b0, 0.f));
                U[(r0 + 8) * 132 + c0 + 1] = f2tf32(fmaxf(acc[mt][nt][3] + b1, 0.f));
            }

        gemm_smemA(U, 132, 128, uow, 128, Bs0, Bs1, acc, tid, wm0, wn0, g, t4);
#pragma unroll
        for (int mt = 0; mt < 4; mt++) {
            const int r0 = wm0 + mt * 16 + g;
            const float al0 = salive[r0];
            const float al1 = salive[r0 + 8];
#pragma unroll
            for (int nt = 0; nt < 4; nt++) {
                const int c0 = wn0 + nt * 8 + 2 * t4;
                const float b0 = uob[c0], b1 = uob[c0 + 1];
                float* p0 = e + (size_t)(br0 + r0) * 128 + c0;
                float* p1 = e + (size_t)(br0 + r0 + 8) * 128 + c0;
                const float2 e0 = *(const float2*)p0;
                const float2 e1 = *(const float2*)p1;
                float2 o0, o1;
                o0.x = (e0.x + fmaxf(acc[mt][nt][0] + b0, 0.f)) * al0;
                o0.y = (e0.y + fmaxf(acc[mt][nt][1] + b1, 0.f)) * al0;
                o1.x = (e1.x + fmaxf(acc[mt][nt][2] + b0, 0.f)) * al1;
                o1.y = (e1.y + fmaxf(acc[mt][nt][3] + b1, 0.f)) * al1;
                *(float2*)p0 = o0;
                *(float2*)p1 = o1;
            }
        }
        __syncthreads();
    }

    for (int p = 0; p < 2; p++) {
        gemm_gmemA(e + (size_t)br0 * 128, 128, 128, v1w + p * 128, 256,
                   As0, As1, Bs0, Bs1, acc, tid, wm0, wn0, g, t4);
#pragma unroll
        for (int mt = 0; mt < 4; mt++)
#pragma unroll
            for (int nt = 0; nt < 4; nt++) {
                const int r0 = wm0 + mt * 16 + g, c0 = wn0 + nt * 8 + 2 * t4;
                const int cg = p * 128 + c0;
                const float b0 = v1b[cg], b1 = v1b[cg + 1];
                U[r0 * 264 + cg]           = f2tf32(fmaxf(acc[mt][nt][0] + b0, 0.f));
                U[r0 * 264 + cg + 1]       = f2tf32(fmaxf(acc[mt][nt][1] + b1, 0.f));
                U[(r0 + 8) * 264 + cg]     = f2tf32(fmaxf(acc[mt][nt][2] + b0, 0.f));
                U[(r0 + 8) * 264 + cg + 1] = f2tf32(fmaxf(acc[mt][nt][3] + b1, 0.f));
            }
    }

    float part[4][2];
#pragma unroll
    for (int mt = 0; mt < 4; mt++) { part[mt][0] = 0.f; part[mt][1] = 0.f; }
    for (int p = 0; p < 2; p++) {
        gemm_smemA(U, 264, 256, v2w + p * 128, 256, Bs0, Bs1, acc, tid, wm0, wn0, g, t4);
#pragma unroll
        for (int mt = 0; mt < 4; mt++)
#pragma unroll
            for (int nt = 0; nt < 4; nt++) {
                const int c0 = wn0 + nt * 8 + 2 * t4;
                const int cg = p * 128 + c0;
                const float b0 = v2b[cg], b1 = v2b[cg + 1];
                const float w0 = vow[cg], w1 = vow[cg + 1];
                part[mt][0] = fmaf(fmaxf(acc[mt][nt][0] + b0, 0.f), w0, part[mt][0]);
                part[mt][0] = fmaf(fmaxf(acc[mt][nt][1] + b1, 0.f), w1, part[mt][0]);
                part[mt][1] = fmaf(fmaxf(acc[mt][nt][2] + b0, 0.f), w0, part[mt][1]);
                part[mt][1] = fmaf(fmaxf(acc[mt][nt][3] + b1, 0.f), w1, part[mt][1]);
            }
    }
#pragma unroll
    for (int mt = 0; mt < 4; mt++)
#pragma unroll
        for (int h = 0; h < 2; h++) {
            part[mt][h] += __shfl_xor_sync(0xffffffffu, part[mt][h], 1);
            part[mt][h] += __shfl_xor_sync(0xffffffffu, part[mt][h], 2);
        }
    __syncthreads();
    if (t4 == 0) {
        const int wn = warp & 3;
#pragma unroll
        for (int mt = 0; mt < 4; mt++)
#pragma unroll
            for (int h = 0; h < 2; h++)
                sred[wn * 128 + wm0 + mt * 16 + g + h * 8] = part[mt][h];
    }
    __syncthreads();
    if (tid < 128) {
        values[br0 + tid] = sred[tid] + sred[128 + tid] + sred[256 + tid]
                          + sred[384 + tid] + __ldg(vob);
    }
}

// ================= launch =================
extern "C" void kernel_launch(void* const* d_in, const int* in_sizes, int n_in,
                              void* d_out, int out_size)
{
    const float* hidden = (const float*)d_in[0];
    const float* obs    = (const float*)d_in[1];
    const int*   dones  = (const int*)d_in[2];
    const float* e1w = (const float*)d_in[3];
    const float* e1b = (const float*)d_in[4];
    const float* e2w = (const float*)d_in[5];
    const float* e2b = (const float*)d_in[6];
    const float* Wi  = (const float*)d_in[7];
    const float* bi  = (const float*)d_in[8];
    const float* Wh  = (const float*)d_in[9];
    const float* bhn = (const float*)d_in[10];
    const float* chw = (const float*)d_in[11];
    const float* chb = (const float*)d_in[12];
    const float* cow = (const float*)d_in[13];
    const float* cob = (const float*)d_in[14];
    const float* uhw = (const float*)d_in[15];
    const float* uhb = (const float*)d_in[16];
    const float* uow = (const float*)d_in[17];
    const float* uob = (const float*)d_in[18];
    const float* v1w = (const float*)d_in[19];
    const float* v1b = (const float*)d_in[20];
    const float* v2w = (const float*)d_in[21];
    const float* v2b = (const float*)d_in[22];
    const float* vow = (const float*)d_in[23];
    const float* vob = (const float*)d_in[24];
    float* out = (float*)d_out;

    float *gi, *e;
    cudaGetSymbolAddress((void**)&gi, g_gi);
    cudaGetSymbolAddress((void**)&e,  g_e);

    const int smE = (2 * 128 * 36 + 2 * 32 * 136 + 128 * 132) * 4;
    const int smM = (2 * 128 * 36 + 2 * 32 * 136 + 128 * 264
                     + 1024 + 128 + 128 + 128 + 512) * 4;
    const int smG = (24576 * 2 + 1024 * 2 + 16 * 392) * 4;
    cudaFuncSetAttribute(embed_gi_fused, cudaFuncAttributeMaxDynamicSharedMemorySize, smE);
    cudaFuncSetAttribute(post_gru_mega,  cudaFuncAttributeMaxDynamicSharedMemorySize, smM);
    cudaFuncSetAttribute(gru_tc,         cudaFuncAttributeMaxDynamicSharedMemorySize, smG);

    embed_gi_fused<<<512, 256, smE>>>(obs, e1w, e1b, e2w, e2b, Wi, bi, gi);
    gru_tc<<<32, 768, smG>>>(gi, dones, Wh, bhn, hidden, e, out);
    post_gru_mega<<<512, 256, smM>>>(e, dones, chw, chb, cow, cob,
                                     uhw, uhb, uow, uob,
                                     v1w, v1b, v2w, v2b, vow, vob, out + 65536);
}